// round 6
// baseline (speedup 1.0000x reference)
#include <cuda_runtime.h>
#include <cuda_bf16.h>

#define DIM 64
#define TSTEPS 1000
#define BATCH 1024
#define MSZ (DIM*DIM)   // 4096

// Power table: M^t for t = 0..1024 (we use 0..999). 1025*4096*4B ~ 16.8 MB.
__device__ float g_pows[1025 * MSZ];

// ---------------------------------------------------------------------------
// 64x64 matmul helper: C = A @ B, 256 threads, 4x4 register tiles.
// A,B,C are smem or gmem float pointers. Syncs at entry and exit.
// ---------------------------------------------------------------------------
__device__ __forceinline__ void mm64(const float* A, const float* B, float* C) {
    __syncthreads();
    int tid = threadIdx.x;
    int i0 = (tid >> 4) << 2;   // 0..60
    int j0 = (tid & 15) << 2;   // 0..60
    float acc[4][4];
#pragma unroll
    for (int r = 0; r < 4; r++)
#pragma unroll
        for (int c = 0; c < 4; c++) acc[r][c] = 0.0f;
#pragma unroll 8
    for (int l = 0; l < 64; l++) {
        float a0 = A[(i0 + 0) * 64 + l];
        float a1 = A[(i0 + 1) * 64 + l];
        float a2 = A[(i0 + 2) * 64 + l];
        float a3 = A[(i0 + 3) * 64 + l];
        float4 b4 = *(const float4*)(B + l * 64 + j0);
        float bb[4] = {b4.x, b4.y, b4.z, b4.w};
#pragma unroll
        for (int c = 0; c < 4; c++) {
            acc[0][c] += a0 * bb[c];
            acc[1][c] += a1 * bb[c];
            acc[2][c] += a2 * bb[c];
            acc[3][c] += a3 * bb[c];
        }
    }
    __syncthreads();   // everyone done reading before C may overwrite
#pragma unroll
    for (int r = 0; r < 4; r++) {
        float4 v = make_float4(acc[r][0], acc[r][1], acc[r][2], acc[r][3]);
        *(float4*)(C + (i0 + r) * 64 + j0) = v;
    }
    __syncthreads();
}

// ---------------------------------------------------------------------------
// Kernel 1: M = expm(K) via degree-14 Paterson-Stockmeyer Taylor.
// ||K|| ~ 0.25 so truncation ~1e-20. Writes g_pows[0] = I, g_pows[1] = M.
// Dynamic smem: 5 * 16KB buffers (K, K2, K3, S, T).
// ---------------------------------------------------------------------------
__global__ void expm_kernel(const float* __restrict__ Kin) {
    extern __shared__ float sm[];
    float* sK  = sm;
    float* sK2 = sm + MSZ;
    float* sK3 = sm + 2 * MSZ;
    float* sS  = sm + 3 * MSZ;
    float* sT  = sm + 4 * MSZ;
    int tid = threadIdx.x;

    // 1/n! for n = 0..14
    const float c[15] = {
        1.0f, 1.0f, 0.5f,
        1.6666666666666666e-1f, 4.1666666666666664e-2f, 8.3333333333333332e-3f,
        1.3888888888888889e-3f, 1.9841269841269841e-4f, 2.4801587301587302e-5f,
        2.7557319223985893e-6f, 2.7557319223985888e-7f, 2.5052108385441720e-8f,
        2.0876756987868100e-9f, 1.6059043836821613e-10f, 1.1470745597729725e-11f
    };

#pragma unroll
    for (int q = 0; q < 16; q++) sK[tid + 256 * q] = Kin[tid + 256 * q];

    mm64(sK, sK, sK2);     // K^2
    mm64(sK2, sK, sK3);    // K^3

    // S = B4 = c12 I + c13 K + c14 K^2
#pragma unroll
    for (int q = 0; q < 16; q++) {
        int e = tid + 256 * q;
        int i = e >> 6, j = e & 63;
        sS[e] = (i == j ? c[12] : 0.0f) + c[13] * sK[e] + c[14] * sK2[e];
    }
    // Horner in K^3: S = B_m + K3 @ S  for m = 3..0
    for (int m = 3; m >= 0; m--) {
        mm64(sK3, sS, sT);
#pragma unroll
        for (int q = 0; q < 16; q++) {
            int e = tid + 256 * q;
            int i = e >> 6, j = e & 63;
            sS[e] = sT[e] + (i == j ? c[3 * m] : 0.0f)
                  + c[3 * m + 1] * sK[e] + c[3 * m + 2] * sK2[e];
        }
        __syncthreads();
    }

    // pows[1] = M, pows[0] = I
#pragma unroll
    for (int q = 0; q < 16; q++) {
        int e = tid + 256 * q;
        int i = e >> 6, j = e & 63;
        g_pows[MSZ + e] = sS[e];
        g_pows[e] = (i == j) ? 1.0f : 0.0f;
    }
}

// ---------------------------------------------------------------------------
// Kernel 2: range doubling. Have pows[0..h-1]; CTA i computes
//   pows[h+i] = pows[h-1] @ pows[i+1]   (powers of M commute; exact M^(h+i))
// ---------------------------------------------------------------------------
__global__ void double_kernel(int h) {
    __shared__ __align__(16) float sA[MSZ];
    __shared__ __align__(16) float sB[MSZ];
    int k = h + blockIdx.x;
    int tid = threadIdx.x;
    const float* A = g_pows + (size_t)(h - 1) * MSZ;
    const float* B = g_pows + (size_t)(k - h + 1) * MSZ;
#pragma unroll
    for (int q = 0; q < 16; q++) {
        int e = tid + 256 * q;
        sA[e] = A[e];
        sB[e] = B[e];
    }
    mm64(sA, sB, g_pows + (size_t)k * MSZ);
}

// ---------------------------------------------------------------------------
// Kernel 3: out[b,t,i] = sum_j M^t[i,j] * x0[b,j]
// Grid (1000, 4). CTA: one t, 256 batch rows. 256 threads.
// Thread: 8 rows (lane + 32r) x 8 cols (warpid*8) via 32 f32x2 accumulators.
// ---------------------------------------------------------------------------
#define XS 260              // x0 smem row stride (conflict-free scalar reads)
#define MS 66               // M^T smem row stride (2-way write conflicts only)
#define GEMM_SMEM ((64 * XS + 64 * MS) * 4)

__global__ __launch_bounds__(256, 2)
void gemm_kernel(const float* __restrict__ x0, float* __restrict__ out) {
    extern __shared__ float smg[];
    float* sX = smg;            // [64][XS]  sX[j*XS + b_local]
    float* sM = smg + 64 * XS;  // [64][MS]  sM[j*MS + i]

    int t = blockIdx.x;
    int b0 = blockIdx.y << 8;
    int tid = threadIdx.x;

    // Stage M^t transposed: sM[j][i] = M[i][j]
    const float* Mg = g_pows + (size_t)t * MSZ;
#pragma unroll
    for (int q = 0; q < 16; q++) {
        int e = tid + 256 * q;
        int i = e >> 6, j = e & 63;
        sM[j * MS + i] = Mg[e];
    }
    // Stage x0 transposed: sX[j][bl] = inputs[(b0+bl)*64000 + j]
#pragma unroll
    for (int q = 0; q < 64; q++) {
        int e = tid + 256 * q;
        int bl = e >> 6, j = e & 63;
        sX[j * XS + bl] = x0[(size_t)(b0 + bl) * (TSTEPS * DIM) + j];
    }
    __syncthreads();

    int lane = tid & 31;        // row lane (rows: lane + 32*r)
    int cg = tid >> 5;          // column group (cols: cg*8 .. cg*8+7)

    unsigned long long acc[8][4];
#pragma unroll
    for (int r = 0; r < 8; r++)
#pragma unroll
        for (int p = 0; p < 4; p++) acc[r][p] = 0ull;

#pragma unroll 4
    for (int j = 0; j < 64; j++) {
        const float* mr = sM + j * MS + (cg << 3);
        unsigned long long m0 = *(const unsigned long long*)(mr + 0);
        unsigned long long m1 = *(const unsigned long long*)(mr + 2);
        unsigned long long m2 = *(const unsigned long long*)(mr + 4);
        unsigned long long m3 = *(const unsigned long long*)(mr + 6);
        const float* xr = sX + j * XS + lane;
#pragma unroll
        for (int r = 0; r < 8; r++) {
            float xv = xr[r * 32];
            unsigned long long x2;
            asm("mov.b64 %0, {%1, %1};" : "=l"(x2) : "f"(xv));
            asm("fma.rn.f32x2 %0, %1, %2, %0;" : "+l"(acc[r][0]) : "l"(x2), "l"(m0));
            asm("fma.rn.f32x2 %0, %1, %2, %0;" : "+l"(acc[r][1]) : "l"(x2), "l"(m1));
            asm("fma.rn.f32x2 %0, %1, %2, %0;" : "+l"(acc[r][2]) : "l"(x2), "l"(m2));
            asm("fma.rn.f32x2 %0, %1, %2, %0;" : "+l"(acc[r][3]) : "l"(x2), "l"(m3));
        }
    }

    // Store: out[b][t][cg*8 .. +7], two 16B stores per row
#pragma unroll
    for (int r = 0; r < 8; r++) {
        size_t b = (size_t)b0 + lane + 32 * r;
        float* o = out + (b * TSTEPS + t) * DIM + (cg << 3);
        ulonglong2 v0; v0.x = acc[r][0]; v0.y = acc[r][1];
        *(ulonglong2*)(o) = v0;
        ulonglong2 v1; v1.x = acc[r][2]; v1.y = acc[r][3];
        *(ulonglong2*)(o + 4) = v1;
    }
}

// ---------------------------------------------------------------------------
extern "C" void kernel_launch(void* const* d_in, const int* in_sizes, int n_in,
                              void* d_out, int out_size) {
    const float* inputs = (const float*)d_in[0];
    const float* kern   = (const float*)d_in[1];
    if (in_sizes[0] == MSZ) {   // defensive: metadata order swap
        const float* tmp = inputs; inputs = kern; kern = tmp;
    }
    float* out = (float*)d_out;

    cudaFuncSetAttribute(expm_kernel, cudaFuncAttributeMaxDynamicSharedMemorySize,
                         5 * MSZ * 4);
    cudaFuncSetAttribute(gemm_kernel, cudaFuncAttributeMaxDynamicSharedMemorySize,
                         GEMM_SMEM);

    expm_kernel<<<1, 256, 5 * MSZ * 4>>>(kern);

    // Range doubling: after a launch at h we have pows[0 .. 2h-2].
    for (int h = 2; h <= TSTEPS - 1; h = 2 * h - 1) {
        int grid = h - 1;
        int remaining = (TSTEPS - 1) - h + 1;   // only need up to t = 999
        if (grid > remaining) grid = remaining;
        if (grid <= 0) break;
        double_kernel<<<grid, 256>>>(h);
    }

    dim3 grid(TSTEPS, BATCH / 256);
    gemm_kernel<<<grid, 256, GEMM_SMEM>>>(inputs, out);
}

// round 9
// speedup vs baseline: 2.2455x; 2.2455x over previous
#include <cuda_runtime.h>
#include <cuda_bf16.h>
#include <cstdint>

#define DIM 64
#define TSTEPS 1000
#define BATCH 1024
#define MSZ (DIM*DIM)   // 4096
#define TLOOP 8

// fp32 power table M^t, t = 0..1024 (doubling kernel operands)
__device__ float g_pows[1025 * MSZ];
// bf16 2-way split of M^t: [t][plane][i*64+j], planes hi/lo
__device__ __align__(16) __nv_bfloat16 g_powsb[TSTEPS * 2 * MSZ];
// bf16 2-way split of x0: [plane][b*64+j]
__device__ __align__(16) __nv_bfloat16 g_x0s[2 * BATCH * DIM];

// ===========================================================================
// helpers
// ===========================================================================
__device__ __forceinline__ uint32_t smem_to_u32(const void* p) {
    uint32_t a;
    asm("{ .reg .u64 t; cvta.to.shared.u64 t, %1; cvt.u32.u64 %0, t; }"
        : "=r"(a) : "l"(p));
    return a;
}

__device__ __forceinline__ void split2(float v, __nv_bfloat16& h, __nv_bfloat16& l) {
    h = __float2bfloat16(v);
    l = __float2bfloat16(v - __bfloat162float(h));
}

// ldmatrix x4: 4 8x8 b16 tiles, addresses from all 32 lanes
#define LDSM_X4(r, addr) \
    asm volatile("ldmatrix.sync.aligned.m8n8.x4.shared.b16 {%0,%1,%2,%3}, [%4];" \
        : "=r"((r)[0]), "=r"((r)[1]), "=r"((r)[2]), "=r"((r)[3]) : "r"(addr))

// bf16 HMMA, fp32 accumulate in place
#define MMA16816(d, a, b) \
    asm volatile("mma.sync.aligned.m16n8k16.row.col.f32.bf16.bf16.f32 " \
        "{%0,%1,%2,%3}, {%4,%5,%6,%7}, {%8,%9}, {%0,%1,%2,%3};" \
        : "+f"((d)[0]), "+f"((d)[1]), "+f"((d)[2]), "+f"((d)[3]) \
        : "r"((a)[0]), "r"((a)[1]), "r"((a)[2]), "r"((a)[3]), \
          "r"((b)[0]), "r"((b)[1]))

// ===========================================================================
// 64x64 matmul helper (smem->smem), 256 threads, 4x4 tiles
// ===========================================================================
__device__ __forceinline__ void mm64(const float* A, const float* B, float* C) {
    __syncthreads();
    int tid = threadIdx.x;
    int i0 = (tid >> 4) << 2;
    int j0 = (tid & 15) << 2;
    float acc[4][4];
#pragma unroll
    for (int r = 0; r < 4; r++)
#pragma unroll
        for (int c = 0; c < 4; c++) acc[r][c] = 0.0f;
#pragma unroll 8
    for (int l = 0; l < 64; l++) {
        float a0 = A[(i0 + 0) * 64 + l];
        float a1 = A[(i0 + 1) * 64 + l];
        float a2 = A[(i0 + 2) * 64 + l];
        float a3 = A[(i0 + 3) * 64 + l];
        float4 b4 = *(const float4*)(B + l * 64 + j0);
        float bb[4] = {b4.x, b4.y, b4.z, b4.w};
#pragma unroll
        for (int c = 0; c < 4; c++) {
            acc[0][c] += a0 * bb[c];
            acc[1][c] += a1 * bb[c];
            acc[2][c] += a2 * bb[c];
            acc[3][c] += a3 * bb[c];
        }
    }
    __syncthreads();
#pragma unroll
    for (int r = 0; r < 4; r++)
        *(float4*)(C + (i0 + r) * 64 + j0) =
            make_float4(acc[r][0], acc[r][1], acc[r][2], acc[r][3]);
    __syncthreads();
}

// ===========================================================================
// Kernel 0: split x0 into bf16 pairs
// ===========================================================================
__global__ void split_x0_kernel(const float* __restrict__ inputs) {
    int idx = blockIdx.x * 256 + threadIdx.x;   // 0..65535
    int b = idx >> 6, j = idx & 63;
    float v = inputs[(size_t)b * (TSTEPS * DIM) + j];
    __nv_bfloat16 h, l;
    split2(v, h, l);
    g_x0s[idx] = h;
    g_x0s[65536 + idx] = l;
}

// ===========================================================================
// Kernel 1: M = expm(K), degree-14 Paterson-Stockmeyer Taylor.
// Writes pows[0]=I, pows[1]=M (fp32 + bf16 splits).
// ===========================================================================
__global__ void expm_kernel(const float* __restrict__ Kin) {
    extern __shared__ float smf[];
    float* sK  = smf;
    float* sK2 = smf + MSZ;
    float* sK3 = smf + 2 * MSZ;
    float* sS  = smf + 3 * MSZ;
    float* sT  = smf + 4 * MSZ;
    int tid = threadIdx.x;

    const float c[15] = {
        1.0f, 1.0f, 0.5f,
        1.6666666666666666e-1f, 4.1666666666666664e-2f, 8.3333333333333332e-3f,
        1.3888888888888889e-3f, 1.9841269841269841e-4f, 2.4801587301587302e-5f,
        2.7557319223985893e-6f, 2.7557319223985888e-7f, 2.5052108385441720e-8f,
        2.0876756987868100e-9f, 1.6059043836821613e-10f, 1.1470745597729725e-11f
    };

#pragma unroll
    for (int q = 0; q < 16; q++) sK[tid + 256 * q] = Kin[tid + 256 * q];

    mm64(sK, sK, sK2);
    mm64(sK2, sK, sK3);

#pragma unroll
    for (int q = 0; q < 16; q++) {
        int e = tid + 256 * q;
        int i = e >> 6, j = e & 63;
        sS[e] = (i == j ? c[12] : 0.0f) + c[13] * sK[e] + c[14] * sK2[e];
    }
    for (int m = 3; m >= 0; m--) {
        mm64(sK3, sS, sT);
#pragma unroll
        for (int q = 0; q < 16; q++) {
            int e = tid + 256 * q;
            int i = e >> 6, j = e & 63;
            sS[e] = sT[e] + (i == j ? c[3 * m] : 0.0f)
                  + c[3 * m + 1] * sK[e] + c[3 * m + 2] * sK2[e];
        }
        __syncthreads();
    }

#pragma unroll
    for (int q = 0; q < 16; q++) {
        int e = tid + 256 * q;
        int i = e >> 6, j = e & 63;
        float idv = (i == j) ? 1.0f : 0.0f;
        float mv = sS[e];
        g_pows[e] = idv;
        g_pows[MSZ + e] = mv;
        // t = 0: identity (exact in bf16)
        g_powsb[e] = __float2bfloat16(idv);
        g_powsb[MSZ + e] = __float2bfloat16(0.0f);
        // t = 1: split of M
        __nv_bfloat16 h, l;
        split2(mv, h, l);
        g_powsb[2 * MSZ + e] = h;
        g_powsb[3 * MSZ + e] = l;
    }
}

// ===========================================================================
// Kernel 2: range doubling. pows[h+i] = pows[h-1] @ pows[i+1].
// Writes fp32 table AND bf16 splits from accumulator registers.
// ===========================================================================
__global__ void double_kernel(int h) {
    __shared__ __align__(16) float sA[MSZ];
    __shared__ __align__(16) float sB[MSZ];
    int k = h + blockIdx.x;
    int tid = threadIdx.x;
    const float* A = g_pows + (size_t)(h - 1) * MSZ;
    const float* B = g_pows + (size_t)(k - h + 1) * MSZ;
#pragma unroll
    for (int q = 0; q < 16; q++) {
        int e = tid + 256 * q;
        sA[e] = A[e];
        sB[e] = B[e];
    }
    __syncthreads();
    int i0 = (tid >> 4) << 2;
    int j0 = (tid & 15) << 2;
    float acc[4][4];
#pragma unroll
    for (int r = 0; r < 4; r++)
#pragma unroll
        for (int c = 0; c < 4; c++) acc[r][c] = 0.0f;
#pragma unroll 8
    for (int l = 0; l < 64; l++) {
        float a0 = sA[(i0 + 0) * 64 + l];
        float a1 = sA[(i0 + 1) * 64 + l];
        float a2 = sA[(i0 + 2) * 64 + l];
        float a3 = sA[(i0 + 3) * 64 + l];
        float4 b4 = *(const float4*)(sB + l * 64 + j0);
        float bb[4] = {b4.x, b4.y, b4.z, b4.w};
#pragma unroll
        for (int c = 0; c < 4; c++) {
            acc[0][c] += a0 * bb[c];
            acc[1][c] += a1 * bb[c];
            acc[2][c] += a2 * bb[c];
            acc[3][c] += a3 * bb[c];
        }
    }
    float* C = g_pows + (size_t)k * MSZ;
    size_t sb = (size_t)k * 2 * MSZ;
#pragma unroll
    for (int r = 0; r < 4; r++) {
#pragma unroll
        for (int c = 0; c < 4; c++) {
            int e = (i0 + r) * 64 + (j0 + c);
            float v = acc[r][c];
            C[e] = v;
            __nv_bfloat16 hh, ll;
            split2(v, hh, ll);
            g_powsb[sb + e] = hh;
            g_powsb[sb + MSZ + e] = ll;
        }
    }
}

// ===========================================================================
// Kernel 3: HMMA (mma.sync bf16x2-split) GEMM.
// CTA: 128 batch x 64 out-dim x TLOOP t's. 256 threads, 8 warps.
// Warp w: batch rows [16w, 16w+16). A-frags register-resident across t loop.
// smem rows padded to 72 bf16 (144B) -> conflict-free ldmatrix.
// ===========================================================================
#define ASTRIDE 144                 // bytes per padded row
#define A_PLANE 18432               // 128 rows * 144B
#define B_PLANE 9216                // 64 rows * 144B
#define SM_B    (2 * A_PLANE)       // 36864: A hi, A lo
#define B_BUF   (2 * B_PLANE)       // 18432 per buffer (hi+lo)
#define SM_TOT  (SM_B + 2 * B_BUF)  // 73728

__global__ __launch_bounds__(256, 2)
void gemm_mma_kernel(float* __restrict__ out) {
    extern __shared__ char smc[];
    uint32_t sbase = smem_to_u32(smc);
    int tid = threadIdx.x;
    int w = tid >> 5, lane = tid & 31;
    int b0 = blockIdx.x << 7;           // batch group (x fastest: sharers concurrent)
    int tbase = blockIdx.y * TLOOP;

    // ---- stage A: 2 planes x 128 rows x 64 bf16, padded rows ----
#pragma unroll
    for (int q = 0; q < 8; q++) {
        int e = tid + 256 * q;          // 0..2047
        int p = e >> 10, rem = e & 1023;
        int row = rem >> 3, c = rem & 7;
        uint4 v = *(const uint4*)(g_x0s + p * (BATCH * DIM) + (b0 + row) * 64 + c * 8);
        *(uint4*)(smc + p * A_PLANE + row * ASTRIDE + c * 16) = v;
    }
    // ---- stage B buffer 0 for t = tbase ----
    {
        const __nv_bfloat16* src = g_powsb + (size_t)tbase * 2 * MSZ;
#pragma unroll
        for (int q = 0; q < 4; q++) {
            int e = tid + 256 * q;      // 0..1023
            int p = e >> 9, rem = e & 511;
            int row = rem >> 3, c = rem & 7;
            uint4 v = *(const uint4*)(src + p * MSZ + row * 64 + c * 8);
            *(uint4*)(smc + SM_B + p * B_PLANE + row * ASTRIDE + c * 16) = v;
        }
    }
    __syncthreads();

    // ---- A fragments, persistent across the whole t loop ----
    // ldmatrix x4 lane map: row = lane&15 (within warp's 16-row block),
    // k-halfblock = lane>>4 (16B).
    uint32_t aH[4][4], aL[4][4];
    {
        uint32_t arow = sbase + (w * 16 + (lane & 15)) * ASTRIDE + (lane >> 4) * 16;
#pragma unroll
        for (int k = 0; k < 4; k++) {
            LDSM_X4(aH[k], arow + k * 32);
            LDSM_X4(aL[k], arow + A_PLANE + k * 32);
        }
    }

    // B ldmatrix x4 lane map (two n-tiles per load):
    // row = p*16 + ((lane>>4)<<3) + (lane&7),  k-halfblock = (lane>>3)&1
    uint32_t brow_off = (((lane >> 4) << 3) + (lane & 7)) * ASTRIDE
                      + ((lane >> 3) & 1) * 16;

    int cur = 0;
#pragma unroll 1
    for (int it = 0; it < TLOOP; it++) {
        int t = tbase + it;

        // ---- prefetch next B into the other buffer ----
        if (it + 1 < TLOOP) {
            const __nv_bfloat16* src = g_powsb + (size_t)(t + 1) * 2 * MSZ;
#pragma unroll
            for (int q = 0; q < 4; q++) {
                int e = tid + 256 * q;
                int p = e >> 9, rem = e & 511;
                int row = rem >> 3, c = rem & 7;
                uint4 v = *(const uint4*)(src + p * MSZ + row * 64 + c * 8);
                *(uint4*)(smc + SM_B + (1 - cur) * B_BUF + p * B_PLANE
                          + row * ASTRIDE + c * 16) = v;
            }
        }

        // ---- compute from current buffer ----
        float acc[8][4];
#pragma unroll
        for (int nt = 0; nt < 8; nt++)
#pragma unroll
            for (int c = 0; c < 4; c++) acc[nt][c] = 0.0f;

        uint32_t bb = sbase + SM_B + cur * B_BUF + brow_off;
#pragma unroll
        for (int k = 0; k < 4; k++) {
            uint32_t bH[8][2], bL[8][2];
#pragma unroll
            for (int p = 0; p < 4; p++) {
                uint32_t addr = bb + p * 16 * ASTRIDE + k * 32;
                LDSM_X4(&bH[2 * p][0], addr);
                LDSM_X4(&bL[2 * p][0], addr + B_PLANE);
            }
#pragma unroll
            for (int nt = 0; nt < 8; nt++) {
                MMA16816(acc[nt], aH[k], bH[nt]);   // hi*hi
                MMA16816(acc[nt], aH[k], bL[nt]);   // hi*lo
                MMA16816(acc[nt], aL[k], bH[nt]);   // lo*hi
            }
        }

        // ---- store C frags: row0 = b0+16w+g, row1 = +8; col = 8nt + 2(lane&3) ----
        {
            int g = lane >> 2, tq = lane & 3;
            size_t r0 = (size_t)b0 + w * 16 + g;
            float* o0 = out + (r0 * TSTEPS + t) * DIM + 2 * tq;
            float* o1 = o0 + (size_t)8 * TSTEPS * DIM;
#pragma unroll
            for (int nt = 0; nt < 8; nt++) {
                *(float2*)(o0 + nt * 8) = make_float2(acc[nt][0], acc[nt][1]);
                *(float2*)(o1 + nt * 8) = make_float2(acc[nt][2], acc[nt][3]);
            }
        }

        __syncthreads();   // prefetch STS done + reads done before buffer swap
        cur ^= 1;
    }
}

// ===========================================================================
extern "C" void kernel_launch(void* const* d_in, const int* in_sizes, int n_in,
                              void* d_out, int out_size) {
    const float* inputs = (const float*)d_in[0];
    const float* kern   = (const float*)d_in[1];
    if (in_sizes[0] == MSZ) {   // defensive: metadata order swap
        const float* tmp = inputs; inputs = kern; kern = tmp;
    }
    float* out = (float*)d_out;

    cudaFuncSetAttribute(expm_kernel, cudaFuncAttributeMaxDynamicSharedMemorySize,
                         5 * MSZ * 4);
    cudaFuncSetAttribute(gemm_mma_kernel, cudaFuncAttributeMaxDynamicSharedMemorySize,
                         SM_TOT);

    split_x0_kernel<<<256, 256>>>(inputs);
    expm_kernel<<<1, 256, 5 * MSZ * 4>>>(kern);

    for (int h = 2; h <= TSTEPS - 1; h = 2 * h - 1) {
        int grid = h - 1;
        int remaining = (TSTEPS - 1) - h + 1;
        if (grid > remaining) grid = remaining;
        if (grid <= 0) break;
        double_kernel<<<grid, 256>>>(h);
    }

    dim3 grid(BATCH / 128, TSTEPS / TLOOP);   // (8, 125)
    gemm_mma_kernel<<<grid, 256, SM_TOT>>>(out);
}